// round 3
// baseline (speedup 1.0000x reference)
#include <cuda_runtime.h>
#include <cuda_bf16.h>

// Problem dims (fixed)
#define Bn   64
#define Tn   512
#define Vn   256
#define En   1024
#define Hn   1024
#define Ln   2
#define H3n  3072
#define Mn   (Bn*Tn)      // 32768
#define NCTA 64

// ---------------- device scratch (static globals; no allocation) ----------------
__device__ __align__(16) float          g_gx[(size_t)Mn*H3n];       // 402 MB (reused per layer)
__device__ __align__(16) __nv_bfloat16  g_x_hi[(size_t)Mn*En];
__device__ __align__(16) __nv_bfloat16  g_x_lo[(size_t)Mn*En];
__device__ __align__(16) __nv_bfloat16  g_y1_hi[(size_t)Mn*Hn];
__device__ __align__(16) __nv_bfloat16  g_y1_lo[(size_t)Mn*Hn];
__device__ __align__(16) __nv_bfloat16  g_y2_hi[(size_t)Mn*Hn];
__device__ __align__(16) __nv_bfloat16  g_y2_lo[(size_t)Mn*Hn];
__device__ __align__(16) float          g_logits[(size_t)Mn*Vn];
__device__ __align__(16) __nv_bfloat16  g_Wih_hi[(size_t)Ln*H3n*Hn];
__device__ __align__(16) __nv_bfloat16  g_Wih_lo[(size_t)Ln*H3n*Hn];
__device__ __align__(16) __nv_bfloat16  g_Whh_hi[(size_t)Ln*H3n*Hn];
__device__ __align__(16) __nv_bfloat16  g_Whh_lo[(size_t)Ln*H3n*Hn];
__device__ __align__(16) __nv_bfloat16  g_Wout_hi[(size_t)Vn*Hn];
__device__ __align__(16) __nv_bfloat16  g_Wout_lo[(size_t)Vn*Hn];
__device__ __align__(16) float          g_h[(size_t)Bn*Hn];
__device__ __align__(16) __nv_bfloat16  g_hh[2][(size_t)Bn*Hn];     // double-buffered h_hi
__device__ __align__(16) __nv_bfloat16  g_hl[2][(size_t)Bn*Hn];     // double-buffered h_lo
__device__ unsigned g_barrier;

// ---------------- helpers ----------------
#define MMA_BF16(d, a, b)                                                     \
  asm volatile("mma.sync.aligned.m16n8k16.row.col.f32.bf16.bf16.f32 "         \
               "{%0,%1,%2,%3},{%4,%5,%6,%7},{%8,%9},{%0,%1,%2,%3};"           \
               : "+f"(d[0]), "+f"(d[1]), "+f"(d[2]), "+f"(d[3])               \
               : "r"(a[0]), "r"(a[1]), "r"(a[2]), "r"(a[3]),                  \
                 "r"(b[0]), "r"(b[1]))

__device__ __forceinline__ unsigned lds_u32(const __nv_bfloat16* s, int row, int ld, int col) {
    return *reinterpret_cast<const unsigned*>(s + row * ld + col);
}

__device__ __forceinline__ void cpa16(void* dst, const void* src) {
    unsigned d = (unsigned)__cvta_generic_to_shared(dst);
    asm volatile("cp.async.cg.shared.global [%0], [%1], 16;\n" :: "r"(d), "l"(src));
}
#define CPA_COMMIT() asm volatile("cp.async.commit_group;\n" ::: "memory")
#define CPA_WAIT(n)  asm volatile("cp.async.wait_group %0;\n" :: "n"(n) : "memory")

// ---------------- elementwise kernels ----------------
__global__ void split_fp32(const float* __restrict__ in,
                           __nv_bfloat16* __restrict__ hi,
                           __nv_bfloat16* __restrict__ lo, int n) {
    int i = blockIdx.x * blockDim.x + threadIdx.x;
    if (i < n) {
        float v = in[i];
        __nv_bfloat16 h = __float2bfloat16(v);
        hi[i] = h;
        lo[i] = __float2bfloat16(v - __bfloat162float(h));
    }
}

__global__ void embed_split(const int* __restrict__ X, const float* __restrict__ emb,
                            __nv_bfloat16* __restrict__ xhi, __nv_bfloat16* __restrict__ xlo) {
    long long i = (long long)blockIdx.x * blockDim.x + threadIdx.x;
    if (i < (long long)Mn * En) {
        int m = (int)(i >> 10);       // En = 1024
        int e = (int)(i & 1023);
        int tok = X[m];
        float v = emb[(size_t)tok * En + e];
        __nv_bfloat16 h = __float2bfloat16(v);
        xhi[i] = h;
        xlo[i] = __float2bfloat16(v - __bfloat162float(h));
    }
}

__global__ void init_h(const float* __restrict__ h0l, float* __restrict__ hbuf,
                       __nv_bfloat16* __restrict__ hhi, __nv_bfloat16* __restrict__ hlo) {
    int i = blockIdx.x * blockDim.x + threadIdx.x;
    if (i == 0) g_barrier = 0u;
    if (i < Bn * Hn) {
        float v = h0l[i];
        hbuf[i] = v;
        __nv_bfloat16 h = __float2bfloat16(v);
        hhi[i] = h;
        hlo[i] = __float2bfloat16(v - __bfloat162float(h));
    }
}

__global__ void copy_out(const float* __restrict__ logits, float* __restrict__ out) {
    int i = blockIdx.x * blockDim.x + threadIdx.x;  // Bn*511*Vn items, exact grid
    int b   = i / (511 * Vn);
    int rem = i - b * (511 * Vn);
    int t   = rem >> 8;      // Vn = 256
    int v   = rem & 255;
    out[i] = logits[(((size_t)b * Tn + t) << 8) + v];
}

// ---------------- big GEMM: C[M,N] = (Ahi+Alo)(Bhi+Blo)^T + bias (split-bf16) ----------------
__global__ __launch_bounds__(256) void gemm_split(
    const __nv_bfloat16* __restrict__ Ahi, const __nv_bfloat16* __restrict__ Alo,
    const __nv_bfloat16* __restrict__ Bhi, const __nv_bfloat16* __restrict__ Blo,
    const float* __restrict__ bias, float* __restrict__ C,
    int Ndim, int Kdim) {
    const int LD = 40;
    __shared__ __nv_bfloat16 sAh[128 * 40], sAl[128 * 40], sBh[64 * 40], sBl[64 * 40];

    int tid = threadIdx.x;
    int warp = tid >> 5, lane = tid & 31;
    int g = lane >> 2, tg = lane & 3;
    int wm = warp >> 1, wn = warp & 1;
    int bm = blockIdx.y * 128, bn = blockIdx.x * 64;

    float acc[2][4][4];
#pragma unroll
    for (int a = 0; a < 2; a++)
#pragma unroll
        for (int b = 0; b < 4; b++)
#pragma unroll
            for (int c = 0; c < 4; c++) acc[a][b][c] = 0.f;

    int cp = tid & 15, r0 = tid >> 4;

    for (int k0 = 0; k0 < Kdim; k0 += 32) {
        __syncthreads();
#pragma unroll
        for (int i = 0; i < 8; i++) {
            int r = r0 + i * 16;
            size_t go = (size_t)(bm + r) * Kdim + k0 + cp * 2;
            *reinterpret_cast<unsigned*>(&sAh[r * LD + cp * 2]) =
                *reinterpret_cast<const unsigned*>(Ahi + go);
            *reinterpret_cast<unsigned*>(&sAl[r * LD + cp * 2]) =
                *reinterpret_cast<const unsigned*>(Alo + go);
        }
#pragma unroll
        for (int i = 0; i < 4; i++) {
            int r = r0 + i * 16;
            size_t go = (size_t)(bn + r) * Kdim + k0 + cp * 2;
            *reinterpret_cast<unsigned*>(&sBh[r * LD + cp * 2]) =
                *reinterpret_cast<const unsigned*>(Bhi + go);
            *reinterpret_cast<unsigned*>(&sBl[r * LD + cp * 2]) =
                *reinterpret_cast<const unsigned*>(Blo + go);
        }
        __syncthreads();

#pragma unroll
        for (int ks = 0; ks < 2; ks++) {
            int kk = ks * 16;
            unsigned ah[2][4], al[2][4], bh[4][2], bl[4][2];
#pragma unroll
            for (int mt = 0; mt < 2; mt++) {
                int r = wm * 32 + mt * 16 + g;
                ah[mt][0] = lds_u32(sAh, r,     LD, kk + tg * 2);
                ah[mt][1] = lds_u32(sAh, r + 8, LD, kk + tg * 2);
                ah[mt][2] = lds_u32(sAh, r,     LD, kk + 8 + tg * 2);
                ah[mt][3] = lds_u32(sAh, r + 8, LD, kk + 8 + tg * 2);
                al[mt][0] = lds_u32(sAl, r,     LD, kk + tg * 2);
                al[mt][1] = lds_u32(sAl, r + 8, LD, kk + tg * 2);
                al[mt][2] = lds_u32(sAl, r,     LD, kk + 8 + tg * 2);
                al[mt][3] = lds_u32(sAl, r + 8, LD, kk + 8 + tg * 2);
            }
#pragma unroll
            for (int nt = 0; nt < 4; nt++) {
                int r = wn * 32 + nt * 8 + g;
                bh[nt][0] = lds_u32(sBh, r, LD, kk + tg * 2);
                bh[nt][1] = lds_u32(sBh, r, LD, kk + 8 + tg * 2);
                bl[nt][0] = lds_u32(sBl, r, LD, kk + tg * 2);
                bl[nt][1] = lds_u32(sBl, r, LD, kk + 8 + tg * 2);
            }
#pragma unroll
            for (int mt = 0; mt < 2; mt++)
#pragma unroll
                for (int nt = 0; nt < 4; nt++) {
                    MMA_BF16(acc[mt][nt], ah[mt], bh[nt]);
                    MMA_BF16(acc[mt][nt], ah[mt], bl[nt]);
                    MMA_BF16(acc[mt][nt], al[mt], bh[nt]);
                }
        }
    }

#pragma unroll
    for (int mt = 0; mt < 2; mt++)
#pragma unroll
        for (int nt = 0; nt < 4; nt++) {
            int r = bm + wm * 32 + mt * 16 + g;
            int cn = bn + wn * 32 + nt * 8 + tg * 2;
            float b0 = bias[cn], b1 = bias[cn + 1];
            *reinterpret_cast<float2*>(&C[(size_t)r * Ndim + cn]) =
                make_float2(acc[mt][nt][0] + b0, acc[mt][nt][1] + b1);
            *reinterpret_cast<float2*>(&C[(size_t)(r + 8) * Ndim + cn]) =
                make_float2(acc[mt][nt][2] + b0, acc[mt][nt][3] + b1);
        }
}

// ---------------- persistent GRU layer kernel ----------------
// 64 CTAs x 128 threads. CTA owns 16 h-cols (48 W_hh rows), W_hh slice resident in SMEM.
// Loops t = 0..511 internally with a software grid barrier.
#define WLD 1032
#define HLD 40
#define SMEM_GRU (48*WLD*2*2 /*W hi+lo*/ + 2*64*HLD*2*2 /*h dbl-buf hi+lo*/ + (64*48+48)*4)

__global__ void __launch_bounds__(128, 1) gru_layer(
    const __nv_bfloat16* __restrict__ Whh_hi, const __nv_bfloat16* __restrict__ Whh_lo,
    const float* __restrict__ bhh, const float* __restrict__ gx,
    __nv_bfloat16* __restrict__ hhB, __nv_bfloat16* __restrict__ hlB,
    float* __restrict__ hbuf,
    __nv_bfloat16* __restrict__ y_hi, __nv_bfloat16* __restrict__ y_lo) {
    extern __shared__ char smem[];
    __nv_bfloat16* sWh = (__nv_bfloat16*)smem;                // 48 x 1032
    __nv_bfloat16* sWl = sWh + 48 * WLD;
    __nv_bfloat16* sHh = sWl + 48 * WLD;                      // 2 bufs x 64 x 40
    __nv_bfloat16* sHl = sHh + 2 * 64 * HLD;
    float*         sGx = (float*)(sHl + 2 * 64 * HLD);        // 64 x 48
    float*         sB  = sGx + 64 * 48;                       // 48

    const int tid  = threadIdx.x;
    const int warp = tid >> 5;
    const int lane = tid & 31;
    const int g    = lane >> 2;
    const int tg   = lane & 3;
    const int c0   = blockIdx.x * 16;
    const size_t HB = (size_t)Bn * Hn;

    // ---- load W_hh slice (hi+lo) into SMEM once ----
    for (int i = tid; i < 48 * 128; i += 128) {
        int r = i >> 7, blk = i & 127;               // row 0..47, 16B-chunk 0..127
        int w = (r >> 4) * 1024 + c0 + (r & 15);     // gate*H + c0 + local
        *reinterpret_cast<uint4*>(sWh + r * WLD + blk * 8) =
            *(reinterpret_cast<const uint4*>(Whh_hi + (size_t)w * Hn) + blk);
        *reinterpret_cast<uint4*>(sWl + r * WLD + blk * 8) =
            *(reinterpret_cast<const uint4*>(Whh_lo + (size_t)w * Hn) + blk);
    }
    if (tid < 48) sB[tid] = bhh[(tid >> 4) * 1024 + c0 + (tid & 15)];
    __syncthreads();

    for (int t = 0; t < Tn; t++) {
        const __nv_bfloat16* hinh = hhB + (size_t)(t & 1) * HB;
        const __nv_bfloat16* hinl = hlB + (size_t)(t & 1) * HB;
        __nv_bfloat16* houth = hhB + (size_t)(1 - (t & 1)) * HB;
        __nv_bfloat16* houtl = hlB + (size_t)(1 - (t & 1)) * HB;

        // ---- prefetch gx tile [64 x 48] for this t ----
#pragma unroll
        for (int p = 0; p < 6; p++) {
            int i = tid + p * 128;
            int row = i / 12, seg = i - row * 12;
            int gate = seg >> 2, part = seg & 3;
            cpa16(sGx + row * 48 + gate * 16 + part * 4,
                  gx + ((size_t)row * Tn + t) * H3n + gate * 1024 + c0 + part * 4);
        }
        CPA_COMMIT();

        // ---- prefetch first h chunk (kc=0 -> buf 0) ----
#pragma unroll
        for (int p = 0; p < 4; p++) {
            int i = tid + p * 128;
            int arr = i >> 8, rem = i & 255;
            int row = rem >> 2, blk = rem & 3;
            const __nv_bfloat16* src = (arr ? hinl : hinh) + (size_t)row * Hn + blk * 8;
            __nv_bfloat16* dst = (arr ? sHl : sHh) + row * HLD + blk * 8;
            cpa16(dst, src);
        }
        CPA_COMMIT();

        float acc[6][4];
#pragma unroll
        for (int a = 0; a < 6; a++)
#pragma unroll
            for (int b = 0; b < 4; b++) acc[a][b] = 0.f;

        const int ar = warp * 16 + g;
        for (int kc = 0; kc < 32; kc++) {
            if (kc < 31) {
#pragma unroll
                for (int p = 0; p < 4; p++) {
                    int i = tid + p * 128;
                    int arr = i >> 8, rem = i & 255;
                    int row = rem >> 2, blk = rem & 3;
                    const __nv_bfloat16* src =
                        (arr ? hinl : hinh) + (size_t)row * Hn + (kc + 1) * 32 + blk * 8;
                    __nv_bfloat16* dst =
                        (arr ? sHl : sHh) + ((kc + 1) & 1) * 64 * HLD + row * HLD + blk * 8;
                    cpa16(dst, src);
                }
                CPA_COMMIT();
                CPA_WAIT(1);
            } else {
                CPA_WAIT(0);
            }
            __syncthreads();

            const __nv_bfloat16* Ah = sHh + (kc & 1) * 64 * HLD;
            const __nv_bfloat16* Al = sHl + (kc & 1) * 64 * HLD;
#pragma unroll
            for (int ks = 0; ks < 2; ks++) {
                int kk = ks * 16;
                unsigned ah[4], al[4];
                ah[0] = lds_u32(Ah, ar,     HLD, kk + tg * 2);
                ah[1] = lds_u32(Ah, ar + 8, HLD, kk + tg * 2);
                ah[2] = lds_u32(Ah, ar,     HLD, kk + 8 + tg * 2);
                ah[3] = lds_u32(Ah, ar + 8, HLD, kk + 8 + tg * 2);
                al[0] = lds_u32(Al, ar,     HLD, kk + tg * 2);
                al[1] = lds_u32(Al, ar + 8, HLD, kk + tg * 2);
                al[2] = lds_u32(Al, ar,     HLD, kk + 8 + tg * 2);
                al[3] = lds_u32(Al, ar + 8, HLD, kk + 8 + tg * 2);
                int kcol = kc * 32 + kk;
#pragma unroll
                for (int nt = 0; nt < 6; nt++) {
                    int rb = nt * 8 + g;
                    unsigned bh[2], bl[2];
                    bh[0] = lds_u32(sWh, rb, WLD, kcol + tg * 2);
                    bh[1] = lds_u32(sWh, rb, WLD, kcol + 8 + tg * 2);
                    bl[0] = lds_u32(sWl, rb, WLD, kcol + tg * 2);
                    bl[1] = lds_u32(sWl, rb, WLD, kcol + 8 + tg * 2);
                    MMA_BF16(acc[nt], ah, bh);
                    MMA_BF16(acc[nt], ah, bl);
                    MMA_BF16(acc[nt], al, bh);
                }
            }
            __syncthreads();
        }

        // ---- epilogue: gates in registers; r=acc[0..1], z=acc[2..3], n=acc[4..5] ----
#pragma unroll
        for (int nt2 = 0; nt2 < 2; nt2++)
#pragma unroll
            for (int half = 0; half < 2; half++)
#pragma unroll
                for (int c = 0; c < 2; c++) {
                    int b  = warp * 16 + g + half * 8;
                    int jl = nt2 * 8 + tg * 2 + c;
                    int j  = c0 + jl;
                    int ai = half * 2 + c;
                    float gr = acc[nt2][ai]     + sB[jl];
                    float gz = acc[nt2 + 2][ai] + sB[16 + jl];
                    float gn = acc[nt2 + 4][ai] + sB[32 + jl];
                    float xr = sGx[b * 48 + jl];
                    float xz = sGx[b * 48 + 16 + jl];
                    float xn = sGx[b * 48 + 32 + jl];
                    float rr = 1.f / (1.f + __expf(-(xr + gr)));
                    float zz = 1.f / (1.f + __expf(-(xz + gz)));
                    float nn = tanhf(xn + rr * gn);
                    float hold = hbuf[b * Hn + j];
                    float hv = (1.f - zz) * nn + zz * hold;
                    hbuf[b * Hn + j] = hv;
                    __nv_bfloat16 hh_ = __float2bfloat16(hv);
                    __nv_bfloat16 hl_ = __float2bfloat16(hv - __bfloat162float(hh_));
                    houth[b * Hn + j] = hh_;
                    houtl[b * Hn + j] = hl_;
                    size_t m = (size_t)b * Tn + t;
                    y_hi[m * Hn + j] = hh_;
                    y_lo[m * Hn + j] = hl_;
                }

        // ---- grid barrier ----
        __threadfence();
        __syncthreads();
        if (tid == 0) {
            atomicAdd(&g_barrier, 1u);
            unsigned tgt = (unsigned)(t + 1) * NCTA;
            while (*(volatile unsigned*)&g_barrier < tgt) { }
        }
        __syncthreads();
        __threadfence();
    }
}

// ---------------- host orchestration ----------------
extern "C" void kernel_launch(void* const* d_in, const int* in_sizes, int n_in,
                              void* d_out, int out_size) {
    (void)in_sizes; (void)n_in; (void)out_size;
    const int*   X     = (const int*)d_in[0];
    const float* h0    = (const float*)d_in[1];
    const float* emb   = (const float*)d_in[2];
    const float* W_ih  = (const float*)d_in[3];
    const float* W_hh  = (const float*)d_in[4];
    const float* b_ih  = (const float*)d_in[5];
    const float* b_hh  = (const float*)d_in[6];
    const float* W_out = (const float*)d_in[7];
    const float* b_out = (const float*)d_in[8];
    float* out = (float*)d_out;

    float *gx, *logits, *hbuf;
    __nv_bfloat16 *xhi, *xlo, *y1hi, *y1lo, *y2hi, *y2lo;
    __nv_bfloat16 *wihH, *wihL, *whhH, *whhL, *woH, *woL;
    __nv_bfloat16 *hhB, *hlB;
    cudaGetSymbolAddress((void**)&gx, g_gx);
    cudaGetSymbolAddress((void**)&logits, g_logits);
    cudaGetSymbolAddress((void**)&hbuf, g_h);
    cudaGetSymbolAddress((void**)&xhi, g_x_hi);
    cudaGetSymbolAddress((void**)&xlo, g_x_lo);
    cudaGetSymbolAddress((void**)&y1hi, g_y1_hi);
    cudaGetSymbolAddress((void**)&y1lo, g_y1_lo);
    cudaGetSymbolAddress((void**)&y2hi, g_y2_hi);
    cudaGetSymbolAddress((void**)&y2lo, g_y2_lo);
    cudaGetSymbolAddress((void**)&wihH, g_Wih_hi);
    cudaGetSymbolAddress((void**)&wihL, g_Wih_lo);
    cudaGetSymbolAddress((void**)&whhH, g_Whh_hi);
    cudaGetSymbolAddress((void**)&whhL, g_Whh_lo);
    cudaGetSymbolAddress((void**)&woH, g_Wout_hi);
    cudaGetSymbolAddress((void**)&woL, g_Wout_lo);
    cudaGetSymbolAddress((void**)&hhB, g_hh);
    cudaGetSymbolAddress((void**)&hlB, g_hl);
    const size_t HB = (size_t)Bn * Hn;

    static int smem_set = 0;
    if (!smem_set) {
        cudaFuncSetAttribute(gru_layer, cudaFuncAttributeMaxDynamicSharedMemorySize, SMEM_GRU);
        smem_set = 1;
    }

    // 1) split weights to (hi, lo) bf16
    int nW = Ln * H3n * Hn;
    split_fp32<<<(nW + 255) / 256, 256>>>(W_ih, wihH, wihL, nW);
    split_fp32<<<(nW + 255) / 256, 256>>>(W_hh, whhH, whhL, nW);
    split_fp32<<<(Vn * Hn + 255) / 256, 256>>>(W_out, woH, woL, Vn * Hn);

    // 2) embedding lookup + split
    embed_split<<<(int)(((long long)Mn * En) / 256), 256>>>(X, emb, xhi, xlo);

    dim3 gg(H3n / 64, Mn / 128);
    for (int l = 0; l < Ln; l++) {
        const __nv_bfloat16* aH = (l == 0) ? xhi : y1hi;
        const __nv_bfloat16* aL = (l == 0) ? xlo : y1lo;
        __nv_bfloat16* yH = (l == 0) ? y1hi : y2hi;
        __nv_bfloat16* yL = (l == 0) ? y1lo : y2lo;
        size_t wOff = (size_t)l * H3n * Hn;

        // input GEMM: gx = A @ W_ih[l]^T + b_ih[l]
        gemm_split<<<gg, 256>>>(aH, aL, wihH + wOff, wihL + wOff,
                                b_ih + (size_t)l * H3n, gx, H3n, Hn);
        // init hidden state + zero barrier
        init_h<<<(Bn * Hn + 255) / 256, 256>>>(h0 + (size_t)l * HB, hbuf, hhB, hlB);
        // persistent recurrence (one launch for all 512 steps)
        gru_layer<<<NCTA, 128, SMEM_GRU>>>(whhH + wOff, whhL + wOff,
                                           b_hh + (size_t)l * H3n, gx,
                                           hhB, hlB, hbuf, yH, yL);
    }

    // output GEMM: logits = y2 @ W_out^T + b_out
    dim3 gl(Vn / 64, Mn / 128);
    gemm_split<<<gl, 256>>>(y2hi, y2lo, woH, woL, b_out, logits, Vn, Hn);

    // drop t = T-1, reshape to [B*(T-1), V]
    copy_out<<<(Bn * 511 * Vn) / 256, 256>>>(logits, out);
}

// round 4
// speedup vs baseline: 1.6374x; 1.6374x over previous
#include <cuda_runtime.h>
#include <cuda_bf16.h>

// Problem dims (fixed)
#define Bn   64
#define Tn   512
#define Vn   256
#define En   1024
#define Hn   1024
#define Ln   2
#define H3n  3072
#define Mn   (Bn*Tn)      // 32768
#define NCTA 128

// ---------------- device scratch (static globals; no allocation) ----------------
__device__ __align__(16) float          g_gx[(size_t)Mn*H3n];       // 402 MB (reused per layer)
__device__ __align__(16) __nv_bfloat16  g_x_hi[(size_t)Mn*En];
__device__ __align__(16) __nv_bfloat16  g_x_lo[(size_t)Mn*En];
__device__ __align__(16) __nv_bfloat16  g_y1_hi[(size_t)Mn*Hn];
__device__ __align__(16) __nv_bfloat16  g_y1_lo[(size_t)Mn*Hn];
__device__ __align__(16) __nv_bfloat16  g_y2_hi[(size_t)Mn*Hn];
__device__ __align__(16) __nv_bfloat16  g_y2_lo[(size_t)Mn*Hn];
__device__ __align__(16) float          g_logits[(size_t)Mn*Vn];
__device__ __align__(16) __nv_bfloat16  g_Wih_hi[(size_t)Ln*H3n*Hn];
__device__ __align__(16) __nv_bfloat16  g_Wih_lo[(size_t)Ln*H3n*Hn];
__device__ __align__(16) __nv_bfloat16  g_Whh_hi[(size_t)Ln*H3n*Hn];
__device__ __align__(16) __nv_bfloat16  g_Whh_lo[(size_t)Ln*H3n*Hn];
__device__ __align__(16) __nv_bfloat16  g_Wout_hi[(size_t)Vn*Hn];
__device__ __align__(16) __nv_bfloat16  g_Wout_lo[(size_t)Vn*Hn];
__device__ __align__(16) __nv_bfloat16  g_h0h[(size_t)Bn*Hn];
__device__ __align__(16) __nv_bfloat16  g_h0l[(size_t)Bn*Hn];
__device__ unsigned g_barrier;

// ---------------- helpers ----------------
#define MMA_BF16(d, a, b)                                                     \
  asm volatile("mma.sync.aligned.m16n8k16.row.col.f32.bf16.bf16.f32 "         \
               "{%0,%1,%2,%3},{%4,%5,%6,%7},{%8,%9},{%0,%1,%2,%3};"           \
               : "+f"(d[0]), "+f"(d[1]), "+f"(d[2]), "+f"(d[3])               \
               : "r"(a[0]), "r"(a[1]), "r"(a[2]), "r"(a[3]),                  \
                 "r"(b[0]), "r"(b[1]))

__device__ __forceinline__ unsigned lds_u32(const __nv_bfloat16* s, int row, int ld, int col) {
    return *reinterpret_cast<const unsigned*>(s + row * ld + col);
}

__device__ __forceinline__ void cpa16(void* dst, const void* src) {
    unsigned d = (unsigned)__cvta_generic_to_shared(dst);
    asm volatile("cp.async.cg.shared.global [%0], [%1], 16;\n" :: "r"(d), "l"(src));
}
#define CPA_COMMIT() asm volatile("cp.async.commit_group;\n" ::: "memory")
#define CPA_WAIT(n)  asm volatile("cp.async.wait_group %0;\n" :: "n"(n) : "memory")

// ---------------- elementwise kernels ----------------
__global__ void split_fp32(const float* __restrict__ in,
                           __nv_bfloat16* __restrict__ hi,
                           __nv_bfloat16* __restrict__ lo, int n) {
    int i = blockIdx.x * blockDim.x + threadIdx.x;
    if (i < n) {
        float v = in[i];
        __nv_bfloat16 h = __float2bfloat16(v);
        hi[i] = h;
        lo[i] = __float2bfloat16(v - __bfloat162float(h));
    }
}

__global__ void embed_split(const int* __restrict__ X, const float* __restrict__ emb,
                            __nv_bfloat16* __restrict__ xhi, __nv_bfloat16* __restrict__ xlo) {
    long long i = (long long)blockIdx.x * blockDim.x + threadIdx.x;
    if (i < (long long)Mn * En) {
        int m = (int)(i >> 10);       // En = 1024
        int e = (int)(i & 1023);
        int tok = X[m];
        float v = emb[(size_t)tok * En + e];
        __nv_bfloat16 h = __float2bfloat16(v);
        xhi[i] = h;
        xlo[i] = __float2bfloat16(v - __bfloat162float(h));
    }
}

__global__ void init_h(const float* __restrict__ h0l,
                       __nv_bfloat16* __restrict__ hhi, __nv_bfloat16* __restrict__ hlo) {
    int i = blockIdx.x * blockDim.x + threadIdx.x;
    if (i == 0) g_barrier = 0u;
    if (i < Bn * Hn) {
        float v = h0l[i];
        __nv_bfloat16 h = __float2bfloat16(v);
        hhi[i] = h;
        hlo[i] = __float2bfloat16(v - __bfloat162float(h));
    }
}

__global__ void copy_out(const float* __restrict__ logits, float* __restrict__ out) {
    int i = blockIdx.x * blockDim.x + threadIdx.x;  // Bn*511*Vn items, exact grid
    int b   = i / (511 * Vn);
    int rem = i - b * (511 * Vn);
    int t   = rem >> 8;      // Vn = 256
    int v   = rem & 255;
    out[i] = logits[(((size_t)b * Tn + t) << 8) + v];
}

// ---------------- big GEMM: C[M,N] = (Ahi+Alo)(Bhi+Blo)^T + bias (split-bf16) ----------------
// BM=128, BN=64, BK=32, 256 threads (8 warps 4m x 2n, warp tile 32x32).
// 3-stage cp.async pipeline, dynamic smem.
#define GLD 40
#define G_STAGE 15360   // elems per stage: (128+128+64+64)*40
#define SMEM_GEMM (3 * G_STAGE * 2)

__device__ __forceinline__ void gemm_load_stage(
    const __nv_bfloat16* Ahi, const __nv_bfloat16* Alo,
    const __nv_bfloat16* Bhi, const __nv_bfloat16* Blo,
    __nv_bfloat16* base, int tid, int bm, int bn, int k0, int Kdim) {
#pragma unroll
    for (int p = 0; p < 4; p++) {
        int i = tid + p * 256;
        int arr = i >> 9;
        int rem = i & 511;
        int row = rem >> 2, ch = rem & 3;
        const __nv_bfloat16* src = (arr ? Alo : Ahi) + (size_t)(bm + row) * Kdim + k0 + ch * 8;
        cpa16(base + arr * 5120 + row * GLD + ch * 8, src);
    }
#pragma unroll
    for (int p = 0; p < 2; p++) {
        int i = tid + p * 256;
        int arr = i >> 8;
        int rem = i & 255;
        int row = rem >> 2, ch = rem & 3;
        const __nv_bfloat16* src = (arr ? Blo : Bhi) + (size_t)(bn + row) * Kdim + k0 + ch * 8;
        cpa16(base + 10240 + arr * 2560 + row * GLD + ch * 8, src);
    }
    CPA_COMMIT();
}

__global__ __launch_bounds__(256, 2) void gemm_split(
    const __nv_bfloat16* __restrict__ Ahi, const __nv_bfloat16* __restrict__ Alo,
    const __nv_bfloat16* __restrict__ Bhi, const __nv_bfloat16* __restrict__ Blo,
    const float* __restrict__ bias, float* __restrict__ C,
    int Ndim, int Kdim) {
    extern __shared__ __nv_bfloat16 dsm[];

    int tid = threadIdx.x;
    int warp = tid >> 5, lane = tid & 31;
    int g = lane >> 2, tg = lane & 3;
    int wm = warp >> 1, wn = warp & 1;
    int bm = blockIdx.y * 128, bn = blockIdx.x * 64;

    float acc[2][4][4];
#pragma unroll
    for (int a = 0; a < 2; a++)
#pragma unroll
        for (int b = 0; b < 4; b++)
#pragma unroll
            for (int c = 0; c < 4; c++) acc[a][b][c] = 0.f;

    int NCk = Kdim >> 5;
    gemm_load_stage(Ahi, Alo, Bhi, Blo, dsm,           tid, bm, bn, 0,  Kdim);
    gemm_load_stage(Ahi, Alo, Bhi, Blo, dsm + G_STAGE, tid, bm, bn, 32, Kdim);

    for (int c = 0; c < NCk; c++) {
        CPA_WAIT(1);
        __syncthreads();
        if (c + 2 < NCk)
            gemm_load_stage(Ahi, Alo, Bhi, Blo, dsm + ((c + 2) % 3) * G_STAGE,
                            tid, bm, bn, (c + 2) * 32, Kdim);

        const __nv_bfloat16* sAh = dsm + (c % 3) * G_STAGE;
        const __nv_bfloat16* sAl = sAh + 5120;
        const __nv_bfloat16* sBh = sAh + 10240;
        const __nv_bfloat16* sBl = sAh + 12800;

#pragma unroll
        for (int ks = 0; ks < 2; ks++) {
            int kk = ks * 16;
            unsigned ah[2][4], al[2][4], bh[4][2], bl[4][2];
#pragma unroll
            for (int mt = 0; mt < 2; mt++) {
                int r = wm * 32 + mt * 16 + g;
                ah[mt][0] = lds_u32(sAh, r,     GLD, kk + tg * 2);
                ah[mt][1] = lds_u32(sAh, r + 8, GLD, kk + tg * 2);
                ah[mt][2] = lds_u32(sAh, r,     GLD, kk + 8 + tg * 2);
                ah[mt][3] = lds_u32(sAh, r + 8, GLD, kk + 8 + tg * 2);
                al[mt][0] = lds_u32(sAl, r,     GLD, kk + tg * 2);
                al[mt][1] = lds_u32(sAl, r + 8, GLD, kk + tg * 2);
                al[mt][2] = lds_u32(sAl, r,     GLD, kk + 8 + tg * 2);
                al[mt][3] = lds_u32(sAl, r + 8, GLD, kk + 8 + tg * 2);
            }
#pragma unroll
            for (int nt = 0; nt < 4; nt++) {
                int r = wn * 32 + nt * 8 + g;
                bh[nt][0] = lds_u32(sBh, r, GLD, kk + tg * 2);
                bh[nt][1] = lds_u32(sBh, r, GLD, kk + 8 + tg * 2);
                bl[nt][0] = lds_u32(sBl, r, GLD, kk + tg * 2);
                bl[nt][1] = lds_u32(sBl, r, GLD, kk + 8 + tg * 2);
            }
#pragma unroll
            for (int mt = 0; mt < 2; mt++)
#pragma unroll
                for (int nt = 0; nt < 4; nt++) {
                    MMA_BF16(acc[mt][nt], ah[mt], bh[nt]);
                    MMA_BF16(acc[mt][nt], ah[mt], bl[nt]);
                    MMA_BF16(acc[mt][nt], al[mt], bh[nt]);
                }
        }
    }

#pragma unroll
    for (int mt = 0; mt < 2; mt++)
#pragma unroll
        for (int nt = 0; nt < 4; nt++) {
            int r = bm + wm * 32 + mt * 16 + g;
            int cn = bn + wn * 32 + nt * 8 + tg * 2;
            float b0 = bias[cn], b1 = bias[cn + 1];
            *reinterpret_cast<float2*>(&C[(size_t)r * Ndim + cn]) =
                make_float2(acc[mt][nt][0] + b0, acc[mt][nt][1] + b1);
            *reinterpret_cast<float2*>(&C[(size_t)(r + 8) * Ndim + cn]) =
                make_float2(acc[mt][nt][2] + b0, acc[mt][nt][3] + b1);
        }
}

// ---------------- persistent GRU layer kernel ----------------
// 128 CTAs x 128 threads (4 warps). CTA owns 8 h-cols (24 W_hh rows) resident in SMEM.
// Each warp owns 16 batch rows; stages its own h tiles (6-stage cp.async, syncwarp only).
// h carried in registers; next-step h read from y[t-1].
#define WLD 1032
#define HLD 40
#define HSTG 6
#define HWRP (HSTG * 2 * 16 * HLD)                       // bf16 elems per warp staging
#define SMEM_GRU (24*WLD*2*2 + 4*HWRP*2 + 64*24*4 + 24*4)

__device__ __forceinline__ void gru_load_h(
    const __nv_bfloat16* hinh, const __nv_bfloat16* hinl, size_t rstride,
    __nv_bfloat16* sHw, int warp, int lane, int chunk, int stage) {
#pragma unroll
    for (int p = 0; p < 4; p++) {
        int i = lane + p * 32;
        int arr = i >> 6;
        int rem = i & 63;
        int row = rem >> 2, ch = rem & 3;
        const __nv_bfloat16* src =
            (arr ? hinl : hinh) + (size_t)(warp * 16 + row) * rstride + chunk * 32 + ch * 8;
        cpa16(sHw + (stage * 2 + arr) * 16 * HLD + row * HLD + ch * 8, src);
    }
    CPA_COMMIT();
}

__global__ void __launch_bounds__(128, 1) gru_layer(
    const __nv_bfloat16* __restrict__ Whh_hi, const __nv_bfloat16* __restrict__ Whh_lo,
    const float* __restrict__ bhh, const float* __restrict__ gx,
    const __nv_bfloat16* __restrict__ h0h, const __nv_bfloat16* __restrict__ h0l,
    const float* __restrict__ h0f,
    __nv_bfloat16* __restrict__ y_hi, __nv_bfloat16* __restrict__ y_lo) {
    extern __shared__ char smem[];
    __nv_bfloat16* sWh = (__nv_bfloat16*)smem;                // 24 x 1032
    __nv_bfloat16* sWl = sWh + 24 * WLD;
    __nv_bfloat16* sH  = sWl + 24 * WLD;                      // [warp][stage][hi/lo][16*40]
    float*         sGx = (float*)(sH + 4 * HWRP);             // [4 warps][16][24]
    float*         sB  = sGx + 64 * 24;                       // 24

    const int tid  = threadIdx.x;
    const int warp = tid >> 5;
    const int lane = tid & 31;
    const int g    = lane >> 2;
    const int tg   = lane & 3;
    const int c0   = blockIdx.x * 8;

    // ---- load W_hh slice (hi+lo) into SMEM once (coalesced, one row per pass) ----
    for (int i = tid; i < 24 * 128; i += 128) {
        int r = i >> 7, blk = i & 127;
        int w = (r >> 3) * 1024 + c0 + (r & 7);      // gate*H + c0 + local
        *reinterpret_cast<uint4*>(sWh + r * WLD + blk * 8) =
            *(reinterpret_cast<const uint4*>(Whh_hi + (size_t)w * Hn) + blk);
        *reinterpret_cast<uint4*>(sWl + r * WLD + blk * 8) =
            *(reinterpret_cast<const uint4*>(Whh_lo + (size_t)w * Hn) + blk);
    }
    if (tid < 24) sB[tid] = bhh[(tid >> 3) * 1024 + c0 + (tid & 7)];

    // ---- h carried in registers: thread owns (b = warp*16+g+{0,8}, j = c0+tg*2+{0,1}) ----
    float hreg[4];
#pragma unroll
    for (int half = 0; half < 2; half++)
#pragma unroll
        for (int c = 0; c < 2; c++)
            hreg[half * 2 + c] = h0f[(warp * 16 + g + half * 8) * Hn + c0 + tg * 2 + c];

    __syncthreads();

    __nv_bfloat16* sHw = sH + warp * HWRP;
    float*         sGw = sGx + warp * 16 * 24;

    for (int t = 0; t < Tn; t++) {
        const __nv_bfloat16* hinh;
        const __nv_bfloat16* hinl;
        size_t rstride;
        if (t == 0) { hinh = h0h; hinl = h0l; rstride = Hn; }
        else {
            hinh = y_hi + (size_t)(t - 1) * Hn;
            hinl = y_lo + (size_t)(t - 1) * Hn;
            rstride = (size_t)Tn * Hn;
        }

        // group: gx tile for this warp (16 rows x 24 f32)
#pragma unroll
        for (int p = 0; p < 3; p++) {
            int i = lane + p * 32;
            int row = i / 6, seg = i % 6;
            int gate = seg >> 1, part = seg & 1;
            cpa16(sGw + row * 24 + gate * 8 + part * 4,
                  gx + ((size_t)(warp * 16 + row) * Tn + t) * H3n + gate * 1024 + c0 + part * 4);
        }
        CPA_COMMIT();

        // prologue: h chunks 0..4
#pragma unroll
        for (int s = 0; s < HSTG - 1; s++)
            gru_load_h(hinh, hinl, rstride, sHw, warp, lane, s, s);

        float acc[3][4];
#pragma unroll
        for (int a = 0; a < 3; a++)
#pragma unroll
            for (int b = 0; b < 4; b++) acc[a][b] = 0.f;

        for (int kc = 0; kc < 32; kc++) {
            if (kc + 5 < 32)
                gru_load_h(hinh, hinl, rstride, sHw, warp, lane, kc + 5, (kc + 5) % HSTG);

            if      (kc < 27)  CPA_WAIT(5);
            else if (kc == 27) CPA_WAIT(4);
            else if (kc == 28) CPA_WAIT(3);
            else if (kc == 29) CPA_WAIT(2);
            else if (kc == 30) CPA_WAIT(1);
            else               CPA_WAIT(0);
            __syncwarp();

            const __nv_bfloat16* Ah = sHw + ((kc % HSTG) * 2 + 0) * 16 * HLD;
            const __nv_bfloat16* Al = sHw + ((kc % HSTG) * 2 + 1) * 16 * HLD;
#pragma unroll
            for (int ks = 0; ks < 2; ks++) {
                int kk = ks * 16;
                unsigned ah[4], al[4];
                ah[0] = lds_u32(Ah, g,     HLD, kk + tg * 2);
                ah[1] = lds_u32(Ah, g + 8, HLD, kk + tg * 2);
                ah[2] = lds_u32(Ah, g,     HLD, kk + 8 + tg * 2);
                ah[3] = lds_u32(Ah, g + 8, HLD, kk + 8 + tg * 2);
                al[0] = lds_u32(Al, g,     HLD, kk + tg * 2);
                al[1] = lds_u32(Al, g + 8, HLD, kk + tg * 2);
                al[2] = lds_u32(Al, g,     HLD, kk + 8 + tg * 2);
                al[3] = lds_u32(Al, g + 8, HLD, kk + 8 + tg * 2);
                int kcol = kc * 32 + kk;
#pragma unroll
                for (int nt = 0; nt < 3; nt++) {
                    int rb = nt * 8 + g;
                    unsigned bh[2], bl[2];
                    bh[0] = lds_u32(sWh, rb, WLD, kcol + tg * 2);
                    bh[1] = lds_u32(sWh, rb, WLD, kcol + 8 + tg * 2);
                    bl[0] = lds_u32(sWl, rb, WLD, kcol + tg * 2);
                    bl[1] = lds_u32(sWl, rb, WLD, kcol + 8 + tg * 2);
                    MMA_BF16(acc[nt], ah, bh);
                    MMA_BF16(acc[nt], ah, bl);
                    MMA_BF16(acc[nt], al, bh);
                }
            }
            __syncwarp();
        }

        // ---- epilogue: gates in registers (acc[0]=r, acc[1]=z, acc[2]=n rows) ----
#pragma unroll
        for (int half = 0; half < 2; half++) {
            __nv_bfloat16 hh2[2], hl2[2];
#pragma unroll
            for (int c = 0; c < 2; c++) {
                int rl = g + half * 8;
                int jl = tg * 2 + c;
                int ai = half * 2 + c;
                float gr = acc[0][ai] + sB[jl];
                float gz = acc[1][ai] + sB[8 + jl];
                float gn = acc[2][ai] + sB[16 + jl];
                float rr = 1.f / (1.f + __expf(-(sGw[rl * 24 + jl] + gr)));
                float zz = 1.f / (1.f + __expf(-(sGw[rl * 24 + 8 + jl] + gz)));
                float nn = tanhf(sGw[rl * 24 + 16 + jl] + rr * gn);
                float hv = (1.f - zz) * nn + zz * hreg[ai];
                hreg[ai] = hv;
                __nv_bfloat16 hh_ = __float2bfloat16(hv);
                hh2[c] = hh_;
                hl2[c] = __float2bfloat16(hv - __bfloat162float(hh_));
            }
            int b = warp * 16 + g + half * 8;
            size_t off = ((size_t)b * Tn + t) * Hn + c0 + tg * 2;
            *reinterpret_cast<__nv_bfloat162*>(y_hi + off) =
                *reinterpret_cast<__nv_bfloat162*>(hh2);
            *reinterpret_cast<__nv_bfloat162*>(y_lo + off) =
                *reinterpret_cast<__nv_bfloat162*>(hl2);
        }

        // ---- grid barrier (skip after last step) ----
        if (t < Tn - 1) {
            __syncthreads();
            if (tid == 0) {
                __threadfence();
                atomicAdd(&g_barrier, 1u);
                unsigned tgt = (unsigned)(t + 1) * NCTA;
                while (*(volatile unsigned*)&g_barrier < tgt) { }
                __threadfence();
            }
            __syncthreads();
        }
    }
}

// ---------------- host orchestration ----------------
extern "C" void kernel_launch(void* const* d_in, const int* in_sizes, int n_in,
                              void* d_out, int out_size) {
    (void)in_sizes; (void)n_in; (void)out_size;
    const int*   X     = (const int*)d_in[0];
    const float* h0    = (const float*)d_in[1];
    const float* emb   = (const float*)d_in[2];
    const float* W_ih  = (const float*)d_in[3];
    const float* W_hh  = (const float*)d_in[4];
    const float* b_ih  = (const float*)d_in[5];
    const float* b_hh  = (const float*)d_in[6];
    const float* W_out = (const float*)d_in[7];
    const float* b_out = (const float*)d_in[8];
    float* out = (float*)d_out;

    float *gx, *logits;
    __nv_bfloat16 *xhi, *xlo, *y1hi, *y1lo, *y2hi, *y2lo;
    __nv_bfloat16 *wihH, *wihL, *whhH, *whhL, *woH, *woL;
    __nv_bfloat16 *h0h, *h0lp;
    cudaGetSymbolAddress((void**)&gx, g_gx);
    cudaGetSymbolAddress((void**)&logits, g_logits);
    cudaGetSymbolAddress((void**)&xhi, g_x_hi);
    cudaGetSymbolAddress((void**)&xlo, g_x_lo);
    cudaGetSymbolAddress((void**)&y1hi, g_y1_hi);
    cudaGetSymbolAddress((void**)&y1lo, g_y1_lo);
    cudaGetSymbolAddress((void**)&y2hi, g_y2_hi);
    cudaGetSymbolAddress((void**)&y2lo, g_y2_lo);
    cudaGetSymbolAddress((void**)&wihH, g_Wih_hi);
    cudaGetSymbolAddress((void**)&wihL, g_Wih_lo);
    cudaGetSymbolAddress((void**)&whhH, g_Whh_hi);
    cudaGetSymbolAddress((void**)&whhL, g_Whh_lo);
    cudaGetSymbolAddress((void**)&woH, g_Wout_hi);
    cudaGetSymbolAddress((void**)&woL, g_Wout_lo);
    cudaGetSymbolAddress((void**)&h0h, g_h0h);
    cudaGetSymbolAddress((void**)&h0lp, g_h0l);
    const size_t HB = (size_t)Bn * Hn;

    cudaFuncSetAttribute(gru_layer, cudaFuncAttributeMaxDynamicSharedMemorySize, SMEM_GRU);
    cudaFuncSetAttribute(gemm_split, cudaFuncAttributeMaxDynamicSharedMemorySize, SMEM_GEMM);

    // 1) split weights to (hi, lo) bf16
    int nW = Ln * H3n * Hn;
    split_fp32<<<(nW + 255) / 256, 256>>>(W_ih, wihH, wihL, nW);
    split_fp32<<<(nW + 255) / 256, 256>>>(W_hh, whhH, whhL, nW);
    split_fp32<<<(Vn * Hn + 255) / 256, 256>>>(W_out, woH, woL, Vn * Hn);

    // 2) embedding lookup + split
    embed_split<<<(int)(((long long)Mn * En) / 256), 256>>>(X, emb, xhi, xlo);

    dim3 gg(H3n / 64, Mn / 128);
    for (int l = 0; l < Ln; l++) {
        const __nv_bfloat16* aH = (l == 0) ? xhi : y1hi;
        const __nv_bfloat16* aL = (l == 0) ? xlo : y1lo;
        __nv_bfloat16* yH = (l == 0) ? y1hi : y2hi;
        __nv_bfloat16* yL = (l == 0) ? y1lo : y2lo;
        size_t wOff = (size_t)l * H3n * Hn;

        // input GEMM: gx = A @ W_ih[l]^T + b_ih[l]
        gemm_split<<<gg, 256, SMEM_GEMM>>>(aH, aL, wihH + wOff, wihL + wOff,
                                           b_ih + (size_t)l * H3n, gx, H3n, Hn);
        // init hidden split + zero barrier
        init_h<<<(Bn * Hn + 255) / 256, 256>>>(h0 + (size_t)l * HB, h0h, h0lp);
        // persistent recurrence (one launch for all 512 steps)
        gru_layer<<<NCTA, 128, SMEM_GRU>>>(whhH + wOff, whhL + wOff,
                                           b_hh + (size_t)l * H3n, gx,
                                           h0h, h0lp, h0 + (size_t)l * HB, yH, yL);
    }

    // output GEMM: logits = y2 @ W_out^T + b_out
    dim3 gl(Vn / 64, Mn / 128);
    gemm_split<<<gl, 256, SMEM_GEMM>>>(y2hi, y2lo, woH, woL, b_out, logits, Vn, Hn);

    // drop t = T-1, reshape to [B*(T-1), V]
    copy_out<<<(Bn * 511 * Vn) / 256, 256>>>(logits, out);
}

// round 6
// speedup vs baseline: 1.9145x; 1.1692x over previous
#include <cuda_runtime.h>
#include <cuda_bf16.h>

// Problem dims (fixed)
#define Bn   64
#define Tn   512
#define Vn   256
#define En   1024
#define Hn   1024
#define Ln   2
#define H3n  3072
#define Mn   (Bn*Tn)      // 32768
#define NCTA 128

// ---------------- device scratch (static globals; no allocation) ----------------
__device__ __align__(16) float          g_gx[(size_t)Mn*H3n];       // 402 MB (reused per layer)
__device__ __align__(16) __nv_bfloat16  g_x_hi[(size_t)Mn*En];
__device__ __align__(16) __nv_bfloat16  g_x_lo[(size_t)Mn*En];
__device__ __align__(16) __nv_bfloat16  g_y1_hi[(size_t)Mn*Hn];
__device__ __align__(16) __nv_bfloat16  g_y1_lo[(size_t)Mn*Hn];
__device__ __align__(16) __nv_bfloat16  g_y2_hi[(size_t)Mn*Hn];
__device__ __align__(16) __nv_bfloat16  g_y2_lo[(size_t)Mn*Hn];
__device__ __align__(16) float          g_logits[(size_t)Mn*Vn];
__device__ __align__(16) __nv_bfloat16  g_Wih_hi[(size_t)Ln*H3n*Hn];
__device__ __align__(16) __nv_bfloat16  g_Wih_lo[(size_t)Ln*H3n*Hn];
__device__ __align__(16) __nv_bfloat16  g_Whh_hi[(size_t)Ln*H3n*Hn];
__device__ __align__(16) __nv_bfloat16  g_Whh_lo[(size_t)Ln*H3n*Hn];
__device__ __align__(16) __nv_bfloat16  g_Wout_hi[(size_t)Vn*Hn];
__device__ __align__(16) __nv_bfloat16  g_Wout_lo[(size_t)Vn*Hn];
__device__ __align__(16) __nv_bfloat16  g_h0h[(size_t)Bn*Hn];
__device__ __align__(16) __nv_bfloat16  g_h0l[(size_t)Bn*Hn];
__device__ unsigned g_barrier;

// ---------------- helpers ----------------
#define MMA_BF16(d, a, b)                                                     \
  asm volatile("mma.sync.aligned.m16n8k16.row.col.f32.bf16.bf16.f32 "         \
               "{%0,%1,%2,%3},{%4,%5,%6,%7},{%8,%9},{%0,%1,%2,%3};"           \
               : "+f"(d[0]), "+f"(d[1]), "+f"(d[2]), "+f"(d[3])               \
               : "r"(a[0]), "r"(a[1]), "r"(a[2]), "r"(a[3]),                  \
                 "r"(b[0]), "r"(b[1]))

__device__ __forceinline__ unsigned lds_u32(const __nv_bfloat16* s, int row, int ld, int col) {
    return *reinterpret_cast<const unsigned*>(s + row * ld + col);
}

__device__ __forceinline__ void cpa16(void* dst, const void* src) {
    unsigned d = (unsigned)__cvta_generic_to_shared(dst);
    asm volatile("cp.async.cg.shared.global [%0], [%1], 16;\n" :: "r"(d), "l"(src));
}
#define CPA_COMMIT() asm volatile("cp.async.commit_group;\n" ::: "memory")
#define CPA_WAIT(n)  asm volatile("cp.async.wait_group %0;\n" :: "n"(n) : "memory")

// ---------------- elementwise kernels ----------------
__global__ void split_fp32(const float* __restrict__ in,
                           __nv_bfloat16* __restrict__ hi,
                           __nv_bfloat16* __restrict__ lo, int n) {
    int i = blockIdx.x * blockDim.x + threadIdx.x;
    if (i < n) {
        float v = in[i];
        __nv_bfloat16 h = __float2bfloat16(v);
        hi[i] = h;
        lo[i] = __float2bfloat16(v - __bfloat162float(h));
    }
}

__global__ void embed_split(const int* __restrict__ X, const float* __restrict__ emb,
                            __nv_bfloat16* __restrict__ xhi, __nv_bfloat16* __restrict__ xlo) {
    long long i = (long long)blockIdx.x * blockDim.x + threadIdx.x;
    if (i < (long long)Mn * En) {
        int m = (int)(i >> 10);
        int e = (int)(i & 1023);
        int tok = X[m];
        float v = emb[(size_t)tok * En + e];
        __nv_bfloat16 h = __float2bfloat16(v);
        xhi[i] = h;
        xlo[i] = __float2bfloat16(v - __bfloat162float(h));
    }
}

__global__ void init_h(const float* __restrict__ h0l,
                       __nv_bfloat16* __restrict__ hhi, __nv_bfloat16* __restrict__ hlo) {
    int i = blockIdx.x * blockDim.x + threadIdx.x;
    if (i == 0) g_barrier = 0u;
    if (i < Bn * Hn) {
        float v = h0l[i];
        __nv_bfloat16 h = __float2bfloat16(v);
        hhi[i] = h;
        hlo[i] = __float2bfloat16(v - __bfloat162float(h));
    }
}

__global__ void copy_out(const float* __restrict__ logits, float* __restrict__ out) {
    int i = blockIdx.x * blockDim.x + threadIdx.x;
    int b   = i / (511 * Vn);
    int rem = i - b * (511 * Vn);
    int t   = rem >> 8;
    int v   = rem & 255;
    out[i] = logits[(((size_t)b * Tn + t) << 8) + v];
}

// ---------------- big GEMM: C[M,N] = (Ahi+Alo)(Bhi+Blo)^T + bias (split-bf16) ----------------
// BM=128, BN=64, BK=32, 256 threads (8 warps 4m x 2n, warp tile 32x32).
// 3-stage cp.async pipeline, dynamic smem. (Known-good from R4.)
#define GLD 40
#define G_STAGE 15360   // elems per stage: (128+128+64+64)*40
#define SMEM_GEMM (3 * G_STAGE * 2)

__device__ __forceinline__ void gemm_load_stage(
    const __nv_bfloat16* Ahi, const __nv_bfloat16* Alo,
    const __nv_bfloat16* Bhi, const __nv_bfloat16* Blo,
    __nv_bfloat16* base, int tid, int bm, int bn, int k0, int Kdim) {
#pragma unroll
    for (int p = 0; p < 4; p++) {
        int i = tid + p * 256;
        int arr = i >> 9;
        int rem = i & 511;
        int row = rem >> 2, ch = rem & 3;
        const __nv_bfloat16* src = (arr ? Alo : Ahi) + (size_t)(bm + row) * Kdim + k0 + ch * 8;
        cpa16(base + arr * 5120 + row * GLD + ch * 8, src);
    }
#pragma unroll
    for (int p = 0; p < 2; p++) {
        int i = tid + p * 256;
        int arr = i >> 8;
        int rem = i & 255;
        int row = rem >> 2, ch = rem & 3;
        const __nv_bfloat16* src = (arr ? Blo : Bhi) + (size_t)(bn + row) * Kdim + k0 + ch * 8;
        cpa16(base + 10240 + arr * 2560 + row * GLD + ch * 8, src);
    }
    CPA_COMMIT();
}

__global__ __launch_bounds__(256, 2) void gemm_split(
    const __nv_bfloat16* __restrict__ Ahi, const __nv_bfloat16* __restrict__ Alo,
    const __nv_bfloat16* __restrict__ Bhi, const __nv_bfloat16* __restrict__ Blo,
    const float* __restrict__ bias, float* __restrict__ C,
    int Ndim, int Kdim) {
    extern __shared__ __nv_bfloat16 dsm[];

    int tid = threadIdx.x;
    int warp = tid >> 5, lane = tid & 31;
    int g = lane >> 2, tg = lane & 3;
    int wm = warp >> 1, wn = warp & 1;
    int bm = blockIdx.y * 128, bn = blockIdx.x * 64;

    float acc[2][4][4];
#pragma unroll
    for (int a = 0; a < 2; a++)
#pragma unroll
        for (int b = 0; b < 4; b++)
#pragma unroll
            for (int c = 0; c < 4; c++) acc[a][b][c] = 0.f;

    int NCk = Kdim >> 5;
    gemm_load_stage(Ahi, Alo, Bhi, Blo, dsm,           tid, bm, bn, 0,  Kdim);
    gemm_load_stage(Ahi, Alo, Bhi, Blo, dsm + G_STAGE, tid, bm, bn, 32, Kdim);

    for (int c = 0; c < NCk; c++) {
        CPA_WAIT(1);
        __syncthreads();
        if (c + 2 < NCk)
            gemm_load_stage(Ahi, Alo, Bhi, Blo, dsm + ((c + 2) % 3) * G_STAGE,
                            tid, bm, bn, (c + 2) * 32, Kdim);

        const __nv_bfloat16* sAh = dsm + (c % 3) * G_STAGE;
        const __nv_bfloat16* sAl = sAh + 5120;
        const __nv_bfloat16* sBh = sAh + 10240;
        const __nv_bfloat16* sBl = sAh + 12800;

#pragma unroll
        for (int ks = 0; ks < 2; ks++) {
            int kk = ks * 16;
            unsigned ah[2][4], al[2][4], bh[4][2], bl[4][2];
#pragma unroll
            for (int mt = 0; mt < 2; mt++) {
                int r = wm * 32 + mt * 16 + g;
                ah[mt][0] = lds_u32(sAh, r,     GLD, kk + tg * 2);
                ah[mt][1] = lds_u32(sAh, r + 8, GLD, kk + tg * 2);
                ah[mt][2] = lds_u32(sAh, r,     GLD, kk + 8 + tg * 2);
                ah[mt][3] = lds_u32(sAh, r + 8, GLD, kk + 8 + tg * 2);
                al[mt][0] = lds_u32(sAl, r,     GLD, kk + tg * 2);
                al[mt][1] = lds_u32(sAl, r + 8, GLD, kk + tg * 2);
                al[mt][2] = lds_u32(sAl, r,     GLD, kk + 8 + tg * 2);
                al[mt][3] = lds_u32(sAl, r + 8, GLD, kk + 8 + tg * 2);
            }
#pragma unroll
            for (int nt = 0; nt < 4; nt++) {
                int r = wn * 32 + nt * 8 + g;
                bh[nt][0] = lds_u32(sBh, r, GLD, kk + tg * 2);
                bh[nt][1] = lds_u32(sBh, r, GLD, kk + 8 + tg * 2);
                bl[nt][0] = lds_u32(sBl, r, GLD, kk + tg * 2);
                bl[nt][1] = lds_u32(sBl, r, GLD, kk + 8 + tg * 2);
            }
#pragma unroll
            for (int mt = 0; mt < 2; mt++)
#pragma unroll
                for (int nt = 0; nt < 4; nt++) {
                    MMA_BF16(acc[mt][nt], ah[mt], bh[nt]);
                    MMA_BF16(acc[mt][nt], ah[mt], bl[nt]);
                    MMA_BF16(acc[mt][nt], al[mt], bh[nt]);
                }
        }
    }

#pragma unroll
    for (int mt = 0; mt < 2; mt++)
#pragma unroll
        for (int nt = 0; nt < 4; nt++) {
            int r = bm + wm * 32 + mt * 16 + g;
            int cn = bn + wn * 32 + nt * 8 + tg * 2;
            float b0 = bias[cn], b1 = bias[cn + 1];
            *reinterpret_cast<float2*>(&C[(size_t)r * Ndim + cn]) =
                make_float2(acc[mt][nt][0] + b0, acc[mt][nt][1] + b1);
            *reinterpret_cast<float2*>(&C[(size_t)(r + 8) * Ndim + cn]) =
                make_float2(acc[mt][nt][2] + b0, acc[mt][nt][3] + b1);
        }
}

// ---------------- persistent GRU layer kernel ----------------
// 128 CTAs x 256 threads (8 warps). CTA owns 8 h-cols (24 W_hh rows) resident in SMEM.
// Warp (rg, kh): rg = warp>>1 owns batch rows rg*16..+16; kh = warp&1 owns K-half kh*512..+512.
// K-split halves the per-warp dependent-MMA chain; warp pairs reduce accs via SMEM.
#define WLD 1032
#define HLD 40
#define HSTG 4
#define HWRP (HSTG * 2 * 16 * HLD)                 // 5120 bf16 per warp staging
#define SMEM_GRU (24*WLD*2*2 + 8*HWRP*2 + 64*24*4 + 24*4 + 4*32*12*4)

__device__ __forceinline__ void gru_load_h(
    const __nv_bfloat16* hinh, const __nv_bfloat16* hinl, size_t rstride,
    __nv_bfloat16* sHw, int rg, int kh, int lane, int chunk, int stage) {
#pragma unroll
    for (int p = 0; p < 4; p++) {
        int i = lane + p * 32;
        int arr = i >> 6;
        int rem = i & 63;
        int row = rem >> 2, ch = rem & 3;
        const __nv_bfloat16* src =
            (arr ? hinl : hinh) + (size_t)(rg * 16 + row) * rstride
            + kh * 512 + chunk * 32 + ch * 8;
        cpa16(sHw + (stage * 2 + arr) * 16 * HLD + row * HLD + ch * 8, src);
    }
    CPA_COMMIT();
}

__global__ void __launch_bounds__(256, 1) gru_layer(
    const __nv_bfloat16* __restrict__ Whh_hi, const __nv_bfloat16* __restrict__ Whh_lo,
    const float* __restrict__ bhh, const float* __restrict__ gx,
    const __nv_bfloat16* __restrict__ h0h, const __nv_bfloat16* __restrict__ h0l,
    const float* __restrict__ h0f,
    __nv_bfloat16* __restrict__ y_hi, __nv_bfloat16* __restrict__ y_lo) {
    extern __shared__ char smem[];
    __nv_bfloat16* sWh = (__nv_bfloat16*)smem;                 // 24 x 1032
    __nv_bfloat16* sWl = sWh + 24 * WLD;
    __nv_bfloat16* sH  = sWl + 24 * WLD;                       // [8 warps][HSTG][hi/lo][16*40]
    float*         sGx = (float*)(sH + 8 * HWRP);              // [64][24]
    float*         sB  = sGx + 64 * 24;                        // 24
    float*         sRed= sB + 24;                              // [4 rg][32 lane][12]

    const int tid  = threadIdx.x;
    const int warp = tid >> 5;
    const int lane = tid & 31;
    const int g    = lane >> 2;
    const int tg   = lane & 3;
    const int rg   = warp >> 1;
    const int kh   = warp & 1;
    const int c0   = blockIdx.x * 8;

    // ---- load W_hh slice (hi+lo) into SMEM once ----
    for (int i = tid; i < 24 * 128; i += 256) {
        int r = i >> 7, blk = i & 127;
        int w = (r >> 3) * 1024 + c0 + (r & 7);
        *reinterpret_cast<uint4*>(sWh + r * WLD + blk * 8) =
            *(reinterpret_cast<const uint4*>(Whh_hi + (size_t)w * Hn) + blk);
        *reinterpret_cast<uint4*>(sWl + r * WLD + blk * 8) =
            *(reinterpret_cast<const uint4*>(Whh_lo + (size_t)w * Hn) + blk);
    }
    if (tid < 24) sB[tid] = bhh[(tid >> 3) * 1024 + c0 + (tid & 7)];

    // h carried in registers by kh==0 warps: b = rg*16+g+{0,8}, j = c0+tg*2+{0,1}
    float hreg[4];
#pragma unroll
    for (int half = 0; half < 2; half++)
#pragma unroll
        for (int c = 0; c < 2; c++)
            hreg[half * 2 + c] = h0f[(rg * 16 + g + half * 8) * Hn + c0 + tg * 2 + c];

    __syncthreads();

    __nv_bfloat16* sHw = sH + warp * HWRP;
    float*         sGw = sGx + rg * 16 * 24;

    for (int t = 0; t < Tn; t++) {
        const __nv_bfloat16* hinh;
        const __nv_bfloat16* hinl;
        size_t rstride;
        if (t == 0) { hinh = h0h; hinl = h0l; rstride = Hn; }
        else {
            hinh = y_hi + (size_t)(t - 1) * Hn;
            hinl = y_lo + (size_t)(t - 1) * Hn;
            rstride = (size_t)Tn * Hn;
        }

        // group 0: gx tile (kh0 loads; kh1 commits empty group to keep counts aligned)
        if (kh == 0) {
#pragma unroll
            for (int p = 0; p < 3; p++) {
                int i = lane + p * 32;
                int row = i / 6, seg = i % 6;
                int gate = seg >> 1, part = seg & 1;
                cpa16(sGw + row * 24 + gate * 8 + part * 4,
                      gx + ((size_t)(rg * 16 + row) * Tn + t) * H3n
                         + gate * 1024 + c0 + part * 4);
            }
        }
        CPA_COMMIT();

        // prologue: h chunks 0..2 of this warp's K-half
#pragma unroll
        for (int s = 0; s < HSTG - 1; s++)
            gru_load_h(hinh, hinl, rstride, sHw, rg, kh, lane, s, s);

        float acc[3][4];
#pragma unroll
        for (int a = 0; a < 3; a++)
#pragma unroll
            for (int b = 0; b < 4; b++) acc[a][b] = 0.f;

        for (int kc = 0; kc < 16; kc++) {
            if (kc + 3 < 16)
                gru_load_h(hinh, hinl, rstride, sHw, rg, kh, lane, kc + 3, (kc + 3) % HSTG);

            if      (kc < 13)  CPA_WAIT(3);
            else if (kc == 13) CPA_WAIT(2);
            else if (kc == 14) CPA_WAIT(1);
            else               CPA_WAIT(0);
            __syncwarp();

            const __nv_bfloat16* Ah = sHw + ((kc % HSTG) * 2 + 0) * 16 * HLD;
            const __nv_bfloat16* Al = sHw + ((kc % HSTG) * 2 + 1) * 16 * HLD;
#pragma unroll
            for (int ks = 0; ks < 2; ks++) {
                int kk = ks * 16;
                unsigned ah[4], al[4];
                ah[0] = lds_u32(Ah, g,     HLD, kk + tg * 2);
                ah[1] = lds_u32(Ah, g + 8, HLD, kk + tg * 2);
                ah[2] = lds_u32(Ah, g,     HLD, kk + 8 + tg * 2);
                ah[3] = lds_u32(Ah, g + 8, HLD, kk + 8 + tg * 2);
                al[0] = lds_u32(Al, g,     HLD, kk + tg * 2);
                al[1] = lds_u32(Al, g + 8, HLD, kk + tg * 2);
                al[2] = lds_u32(Al, g,     HLD, kk + 8 + tg * 2);
                al[3] = lds_u32(Al, g + 8, HLD, kk + 8 + tg * 2);
                int kcol = kh * 512 + kc * 32 + kk;
#pragma unroll
                for (int nt = 0; nt < 3; nt++) {
                    int rb = nt * 8 + g;
                    unsigned bh[2], bl[2];
                    bh[0] = lds_u32(sWh, rb, WLD, kcol + tg * 2);
                    bh[1] = lds_u32(sWh, rb, WLD, kcol + 8 + tg * 2);
                    bl[0] = lds_u32(sWl, rb, WLD, kcol + tg * 2);
                    bl[1] = lds_u32(sWl, rb, WLD, kcol + 8 + tg * 2);
                    MMA_BF16(acc[nt], ah, bh);
                    MMA_BF16(acc[nt], ah, bl);
                    MMA_BF16(acc[nt], al, bh);
                }
            }
            __syncwarp();
        }

        // ---- cross-K-half reduction: kh1 stores, kh0 adds ----
        if (kh == 1) {
            float* r = sRed + (rg * 32 + lane) * 12;
#pragma unroll
            for (int nt = 0; nt < 3; nt++)
#pragma unroll
                for (int i = 0; i < 4; i++) r[nt * 4 + i] = acc[nt][i];
        }
        __syncthreads();

        if (kh == 0) {
            const float* r = sRed + (rg * 32 + lane) * 12;
#pragma unroll
            for (int nt = 0; nt < 3; nt++)
#pragma unroll
                for (int i = 0; i < 4; i++) acc[nt][i] += r[nt * 4 + i];

            // ---- epilogue: gates in registers ----
#pragma unroll
            for (int half = 0; half < 2; half++) {
                __nv_bfloat16 hh2[2], hl2[2];
#pragma unroll
                for (int c = 0; c < 2; c++) {
                    int rl = g + half * 8;
                    int jl = tg * 2 + c;
                    int ai = half * 2 + c;
                    float gr = acc[0][ai] + sB[jl];
                    float gz = acc[1][ai] + sB[8 + jl];
                    float gn = acc[2][ai] + sB[16 + jl];
                    float rr = 1.f / (1.f + __expf(-(sGw[rl * 24 + jl] + gr)));
                    float zz = 1.f / (1.f + __expf(-(sGw[rl * 24 + 8 + jl] + gz)));
                    float nn = tanhf(sGw[rl * 24 + 16 + jl] + rr * gn);
                    float hv = (1.f - zz) * nn + zz * hreg[ai];
                    hreg[ai] = hv;
                    __nv_bfloat16 hh_ = __float2bfloat16(hv);
                    hh2[c] = hh_;
                    hl2[c] = __float2bfloat16(hv - __bfloat162float(hh_));
                }
                int b = rg * 16 + g + half * 8;
                size_t off = ((size_t)b * Tn + t) * Hn + c0 + tg * 2;
                *reinterpret_cast<__nv_bfloat162*>(y_hi + off) =
                    *reinterpret_cast<__nv_bfloat162*>(hh2);
                *reinterpret_cast<__nv_bfloat162*>(y_lo + off) =
                    *reinterpret_cast<__nv_bfloat162*>(hl2);
            }
        }

        // ---- grid barrier (skip after last step) ----
        if (t < Tn - 1) {
            __syncthreads();
            if (tid == 0) {
                __threadfence();
                atomicAdd(&g_barrier, 1u);
                unsigned tgt = (unsigned)(t + 1) * NCTA;
                while (*(volatile unsigned*)&g_barrier < tgt) { }
                __threadfence();
            }
            __syncthreads();
        }
    }
}

// ---------------- host orchestration ----------------
extern "C" void kernel_launch(void* const* d_in, const int* in_sizes, int n_in,
                              void* d_out, int out_size) {
    (void)in_sizes; (void)n_in; (void)out_size;
    const int*   X     = (const int*)d_in[0];
    const float* h0    = (const float*)d_in[1];
    const float* emb   = (const float*)d_in[2];
    const float* W_ih  = (const float*)d_in[3];
    const float* W_hh  = (const float*)d_in[4];
    const float* b_ih  = (const float*)d_in[5];
    const float* b_hh  = (const float*)d_in[6];
    const float* W_out = (const float*)d_in[7];
    const float* b_out = (const float*)d_in[8];
    float* out = (float*)d_out;

    float *gx, *logits;
    __nv_bfloat16 *xhi, *xlo, *y1hi, *y1lo, *y2hi, *y2lo;
    __nv_bfloat16 *wihH, *wihL, *whhH, *whhL, *woH, *woL;
    __nv_bfloat16 *h0h, *h0lp;
    cudaGetSymbolAddress((void**)&gx, g_gx);
    cudaGetSymbolAddress((void**)&logits, g_logits);
    cudaGetSymbolAddress((void**)&xhi, g_x_hi);
    cudaGetSymbolAddress((void**)&xlo, g_x_lo);
    cudaGetSymbolAddress((void**)&y1hi, g_y1_hi);
    cudaGetSymbolAddress((void**)&y1lo, g_y1_lo);
    cudaGetSymbolAddress((void**)&y2hi, g_y2_hi);
    cudaGetSymbolAddress((void**)&y2lo, g_y2_lo);
    cudaGetSymbolAddress((void**)&wihH, g_Wih_hi);
    cudaGetSymbolAddress((void**)&wihL, g_Wih_lo);
    cudaGetSymbolAddress((void**)&whhH, g_Whh_hi);
    cudaGetSymbolAddress((void**)&whhL, g_Whh_lo);
    cudaGetSymbolAddress((void**)&woH, g_Wout_hi);
    cudaGetSymbolAddress((void**)&woL, g_Wout_lo);
    cudaGetSymbolAddress((void**)&h0h, g_h0h);
    cudaGetSymbolAddress((void**)&h0lp, g_h0l);
    const size_t HB = (size_t)Bn * Hn;

    cudaFuncSetAttribute(gru_layer, cudaFuncAttributeMaxDynamicSharedMemorySize, SMEM_GRU);
    cudaFuncSetAttribute(gemm_split, cudaFuncAttributeMaxDynamicSharedMemorySize, SMEM_GEMM);

    // 1) split weights to (hi, lo) bf16
    int nW = Ln * H3n * Hn;
    split_fp32<<<(nW + 255) / 256, 256>>>(W_ih, wihH, wihL, nW);
    split_fp32<<<(nW + 255) / 256, 256>>>(W_hh, whhH, whhL, nW);
    split_fp32<<<(Vn * Hn + 255) / 256, 256>>>(W_out, woH, woL, Vn * Hn);

    // 2) embedding lookup + split
    embed_split<<<(int)(((long long)Mn * En) / 256), 256>>>(X, emb, xhi, xlo);

    dim3 gg(H3n / 64, Mn / 128);
    for (int l = 0; l < Ln; l++) {
        const __nv_bfloat16* aH = (l == 0) ? xhi : y1hi;
        const __nv_bfloat16* aL = (l == 0) ? xlo : y1lo;
        __nv_bfloat16* yH = (l == 0) ? y1hi : y2hi;
        __nv_bfloat16* yL = (l == 0) ? y1lo : y2lo;
        size_t wOff = (size_t)l * H3n * Hn;

        // input GEMM: gx = A @ W_ih[l]^T + b_ih[l]
        gemm_split<<<gg, 256, SMEM_GEMM>>>(aH, aL, wihH + wOff, wihL + wOff,
                                           b_ih + (size_t)l * H3n, gx, H3n, Hn);
        // init hidden split + zero barrier
        init_h<<<(Bn * Hn + 255) / 256, 256>>>(h0 + (size_t)l * HB, h0h, h0lp);
        // persistent recurrence (one launch for all 512 steps)
        gru_layer<<<NCTA, 256, SMEM_GRU>>>(whhH + wOff, whhL + wOff,
                                           b_hh + (size_t)l * H3n, gx,
                                           h0h, h0lp, h0 + (size_t)l * HB, yH, yL);
    }

    // output GEMM: logits = y2 @ W_out^T + b_out
    dim3 gl(Vn / 64, Mn / 128);
    gemm_split<<<gl, 256, SMEM_GEMM>>>(y2hi, y2lo, woH, woL, b_out, logits, Vn, Hn);

    // drop t = T-1, reshape to [B*(T-1), V]
    copy_out<<<(Bn * 511 * Vn) / 256, 256>>>(logits, out);
}